// round 3
// baseline (speedup 1.0000x reference)
#include <cuda_runtime.h>

// 2-layer LSTM (IN=16, H=32, T=512, B=4096) + MLP head, fully fused.
// R3: warp = 2 sequences (2 groups x 16 lanes) -> 2048 warps (14/SM) for
// latency hiding; R2 had only 1024 warps (7/SM, issue=25%).
// Lane i of a group owns hidden units {i, i+16} of its group's sequence.
// Weights in smem gate-packed float4; gate math in packed fma.rn.f32x2.

#define FULLMASK 0xffffffffu

constexpr int T_LEN = 512;
constexpr int IN_DIM = 16;
constexpr int H_DIM = 32;
constexpr int SEQ_PER_WARP = 2;
constexpr int WARPS_PER_BLOCK = 14;  // 147 blocks x 14 = 2058 warps >= 2048
constexpr int THREADS = WARPS_PER_BLOCK * 32;

struct SmemW {
    float4 wih0[IN_DIM][H_DIM];  // [row k][unit u] = gates (i,f,g,o)
    float4 whh0[H_DIM][H_DIM];
    float4 wih1[H_DIM][H_DIM];
    float4 whh1[H_DIM][H_DIM];
    float4 bg0[H_DIM];           // bih0+bhh0, gate-packed
    float4 bg1[H_DIM];
};

typedef unsigned long long u64;

__device__ __forceinline__ u64 fma2(u64 a, u64 b, u64 c) {
    u64 d;
    asm("fma.rn.f32x2 %0, %1, %2, %3;" : "=l"(d) : "l"(a), "l"(b), "l"(c));
    return d;
}
__device__ __forceinline__ u64 pack2(float v) {
    u64 r;
    asm("mov.b64 %0, {%1, %1};" : "=l"(r) : "f"(v));
    return r;
}
__device__ __forceinline__ float2 unpack2(u64 v) {
    float2 r;
    asm("mov.b64 {%0, %1}, %2;" : "=f"(r.x), "=f"(r.y) : "l"(v));
    return r;
}

__device__ __forceinline__ float fast_sigmoid(float x) {
    return __fdividef(1.0f, 1.0f + __expf(-x));
}
__device__ __forceinline__ float fast_tanh(float x) {
    float a = fabsf(x);
    float e = __expf(-2.0f * a);
    float r = __fdividef(1.0f - e, 1.0f + e);
    return copysignf(r, x);
}

__device__ __forceinline__ void lstm_cell(u64 a_if, u64 a_go, float& h, float& c) {
    float2 if_ = unpack2(a_if);
    float2 go  = unpack2(a_go);
    float ig = fast_sigmoid(if_.x);
    float fg = fast_sigmoid(if_.y);
    float gg = fast_tanh(go.x);
    float og = fast_sigmoid(go.y);
    c = fmaf(fg, c, ig * gg);
    h = og * fast_tanh(c);
}

__global__ void __launch_bounds__(THREADS, 1)
lstm_fused_kernel(const float* __restrict__ x,
                  const float* __restrict__ Wih0, const float* __restrict__ Whh0,
                  const float* __restrict__ bih0, const float* __restrict__ bhh0,
                  const float* __restrict__ Wih1, const float* __restrict__ Whh1,
                  const float* __restrict__ bih1, const float* __restrict__ bhh1,
                  const float* __restrict__ W1, const float* __restrict__ b1,
                  const float* __restrict__ W2, const float* __restrict__ b2,
                  float* __restrict__ out, int batch) {
    extern __shared__ char smem_raw[];
    SmemW* s = reinterpret_cast<SmemW*>(smem_raw);

    const int tid = threadIdx.x;

    // ---- Stage weights: gate-packed float4 per (row, unit) ----
    for (int i = tid; i < IN_DIM * H_DIM; i += THREADS) {
        int k = i / H_DIM, u = i % H_DIM;
        s->wih0[k][u] = make_float4(Wih0[(0 * H_DIM + u) * IN_DIM + k],
                                    Wih0[(1 * H_DIM + u) * IN_DIM + k],
                                    Wih0[(2 * H_DIM + u) * IN_DIM + k],
                                    Wih0[(3 * H_DIM + u) * IN_DIM + k]);
    }
    for (int i = tid; i < H_DIM * H_DIM; i += THREADS) {
        int j = i / H_DIM, u = i % H_DIM;
        s->whh0[j][u] = make_float4(Whh0[(0 * H_DIM + u) * H_DIM + j],
                                    Whh0[(1 * H_DIM + u) * H_DIM + j],
                                    Whh0[(2 * H_DIM + u) * H_DIM + j],
                                    Whh0[(3 * H_DIM + u) * H_DIM + j]);
        s->wih1[j][u] = make_float4(Wih1[(0 * H_DIM + u) * H_DIM + j],
                                    Wih1[(1 * H_DIM + u) * H_DIM + j],
                                    Wih1[(2 * H_DIM + u) * H_DIM + j],
                                    Wih1[(3 * H_DIM + u) * H_DIM + j]);
        s->whh1[j][u] = make_float4(Whh1[(0 * H_DIM + u) * H_DIM + j],
                                    Whh1[(1 * H_DIM + u) * H_DIM + j],
                                    Whh1[(2 * H_DIM + u) * H_DIM + j],
                                    Whh1[(3 * H_DIM + u) * H_DIM + j]);
    }
    for (int u = tid; u < H_DIM; u += THREADS) {
        s->bg0[u] = make_float4(bih0[0 * H_DIM + u] + bhh0[0 * H_DIM + u],
                                bih0[1 * H_DIM + u] + bhh0[1 * H_DIM + u],
                                bih0[2 * H_DIM + u] + bhh0[2 * H_DIM + u],
                                bih0[3 * H_DIM + u] + bhh0[3 * H_DIM + u]);
        s->bg1[u] = make_float4(bih1[0 * H_DIM + u] + bhh1[0 * H_DIM + u],
                                bih1[1 * H_DIM + u] + bhh1[1 * H_DIM + u],
                                bih1[2 * H_DIM + u] + bhh1[2 * H_DIM + u],
                                bih1[3 * H_DIM + u] + bhh1[3 * H_DIM + u]);
    }
    __syncthreads();

    const int warp = tid >> 5;
    const int lane = tid & 31;
    const int i16 = lane & 15;        // lane within group: owns units i16, i16+16
    const int g2 = lane >> 4;         // group 0..1 = sequence within warp
    const int wglobal = blockIdx.x * WARPS_PER_BLOCK + warp;
    const int seq_base = wglobal * SEQ_PER_WARP;
    if (seq_base >= batch) return;    // whole warp out (batch % 2 == 0)
    const int b = seq_base + g2;

    const float* xb = x + (size_t)b * T_LEN * IN_DIM;

    float h0[2] = {0.f, 0.f};
    float c0[2] = {0.f, 0.f};
    float h1[2] = {0.f, 0.f};
    float c1[2] = {0.f, 0.f};

    // x regs: lane i16 holds x[i16] of its group's sequence (IN_DIM == 16).
    float xv = __ldg(xb + i16);

    for (int t = 0; t < T_LEN; t++) {
        float xn = 0.f;
        if (t + 1 < T_LEN) xn = __ldg(xb + (t + 1) * IN_DIM + i16);

        // ================= Layer 0 =================
        u64 a0[2][2];
#pragma unroll
        for (int uu = 0; uu < 2; uu++) {
            ulonglong2 bb = *reinterpret_cast<const ulonglong2*>(&s->bg0[i16 + 16 * uu]);
            a0[uu][0] = bb.x;
            a0[uu][1] = bb.y;
        }
#pragma unroll
        for (int k = 0; k < IN_DIM; k++) {
            float xk = __shfl_sync(FULLMASK, xv, k, 16);
            u64 xk2 = pack2(xk);
#pragma unroll
            for (int uu = 0; uu < 2; uu++) {
                ulonglong2 w = *reinterpret_cast<const ulonglong2*>(&s->wih0[k][i16 + 16 * uu]);
                a0[uu][0] = fma2(w.x, xk2, a0[uu][0]);
                a0[uu][1] = fma2(w.y, xk2, a0[uu][1]);
            }
        }
#pragma unroll
        for (int j = 0; j < H_DIM; j++) {
            float hj = __shfl_sync(FULLMASK, h0[j >> 4], j & 15, 16);
            u64 hj2 = pack2(hj);
#pragma unroll
            for (int uu = 0; uu < 2; uu++) {
                ulonglong2 w = *reinterpret_cast<const ulonglong2*>(&s->whh0[j][i16 + 16 * uu]);
                a0[uu][0] = fma2(w.x, hj2, a0[uu][0]);
                a0[uu][1] = fma2(w.y, hj2, a0[uu][1]);
            }
        }
        float h0n[2];
#pragma unroll
        for (int uu = 0; uu < 2; uu++)
            lstm_cell(a0[uu][0], a0[uu][1], h0n[uu], c0[uu]);

        // ================= Layer 1 =================
        u64 a1[2][2];
#pragma unroll
        for (int uu = 0; uu < 2; uu++) {
            ulonglong2 bb = *reinterpret_cast<const ulonglong2*>(&s->bg1[i16 + 16 * uu]);
            a1[uu][0] = bb.x;
            a1[uu][1] = bb.y;
        }
#pragma unroll
        for (int j = 0; j < H_DIM; j++) {
            float hj = __shfl_sync(FULLMASK, h0n[j >> 4], j & 15, 16);
            u64 hj2 = pack2(hj);
#pragma unroll
            for (int uu = 0; uu < 2; uu++) {
                ulonglong2 w = *reinterpret_cast<const ulonglong2*>(&s->wih1[j][i16 + 16 * uu]);
                a1[uu][0] = fma2(w.x, hj2, a1[uu][0]);
                a1[uu][1] = fma2(w.y, hj2, a1[uu][1]);
            }
        }
#pragma unroll
        for (int j = 0; j < H_DIM; j++) {
            float hj = __shfl_sync(FULLMASK, h1[j >> 4], j & 15, 16);
            u64 hj2 = pack2(hj);
#pragma unroll
            for (int uu = 0; uu < 2; uu++) {
                ulonglong2 w = *reinterpret_cast<const ulonglong2*>(&s->whh1[j][i16 + 16 * uu]);
                a1[uu][0] = fma2(w.x, hj2, a1[uu][0]);
                a1[uu][1] = fma2(w.y, hj2, a1[uu][1]);
            }
        }
#pragma unroll
        for (int uu = 0; uu < 2; uu++) {
            lstm_cell(a1[uu][0], a1[uu][1], h1[uu], c1[uu]);
            h0[uu] = h0n[uu];
        }

        xv = xn;
    }

    // ---- Head: z = relu(h1 @ W1.T + b1); y = z @ W2.T + b2 ----
    // Lane i16 computes head output m = i16 for its group's sequence.
    float z = __ldg(b1 + i16);
#pragma unroll
    for (int j = 0; j < H_DIM; j++) {
        float hj = __shfl_sync(FULLMASK, h1[j >> 4], j & 15, 16);
        z = fmaf(__ldg(W1 + i16 * H_DIM + j), hj, z);
    }
    z = fmaxf(z, 0.f);
    float val = z * __ldg(W2 + i16);
#pragma unroll
    for (int off = 8; off >= 1; off >>= 1)
        val += __shfl_xor_sync(FULLMASK, val, off, 16);
    if (i16 == 0) out[b] = val + __ldg(b2);
}

extern "C" void kernel_launch(void* const* d_in, const int* in_sizes, int n_in,
                              void* d_out, int out_size) {
    const float* x    = (const float*)d_in[0];
    const float* Wih0 = (const float*)d_in[1];
    const float* Whh0 = (const float*)d_in[2];
    const float* bih0 = (const float*)d_in[3];
    const float* bhh0 = (const float*)d_in[4];
    const float* Wih1 = (const float*)d_in[5];
    const float* Whh1 = (const float*)d_in[6];
    const float* bih1 = (const float*)d_in[7];
    const float* bhh1 = (const float*)d_in[8];
    const float* W1   = (const float*)d_in[9];
    const float* b1   = (const float*)d_in[10];
    const float* W2   = (const float*)d_in[11];
    const float* b2   = (const float*)d_in[12];
    float* out = (float*)d_out;

    int batch = in_sizes[0] / (T_LEN * IN_DIM);  // 4096

    cudaFuncSetAttribute(lstm_fused_kernel,
                         cudaFuncAttributeMaxDynamicSharedMemorySize,
                         (int)sizeof(SmemW));

    int warps_needed = (batch + SEQ_PER_WARP - 1) / SEQ_PER_WARP;        // 2048
    int blocks = (warps_needed + WARPS_PER_BLOCK - 1) / WARPS_PER_BLOCK; // 147
    lstm_fused_kernel<<<blocks, THREADS, sizeof(SmemW)>>>(
        x, Wih0, Whh0, bih0, bhh0, Wih1, Whh1, bih1, bhh1,
        W1, b1, W2, b2, out, batch);
}

// round 4
// speedup vs baseline: 1.2458x; 1.2458x over previous
#include <cuda_runtime.h>

// 2-layer LSTM (IN=16, H=32, T=512, B=4096) + MLP head, fully fused.
// R4: lane = hidden unit (32 lanes = 32 units); warp = 8 sequences packed as
// 4 f32x2 seq-pairs. Each LDS.128 fetches one unit's 4 gate weights for one
// input dim and is reused across all 8 sequences (16 FFMA2 per LDS) -> smem
// return traffic drops 4x vs R2/R3 (the measured 36 TB/s L1-return wall).
// Activations (h-state) are seq-pair packed u64 and broadcast via 64-bit shfl.

#define FULLMASK 0xffffffffu

constexpr int T_LEN = 512;
constexpr int IN_DIM = 16;
constexpr int H_DIM = 32;
constexpr int SEQ_PER_WARP = 8;
constexpr int WARPS_PER_BLOCK = 4;
constexpr int THREADS = WARPS_PER_BLOCK * 32;

struct SmemW {
    float4 wih0[IN_DIM][H_DIM];  // [dim][unit] = (wi,wf,wg,wo)
    float4 whh0[H_DIM][H_DIM];
    float4 wih1[H_DIM][H_DIM];
    float4 whh1[H_DIM][H_DIM];
    float4 bg0[H_DIM];           // bih0+bhh0 per unit, gate-packed
    float4 bg1[H_DIM];
};

typedef unsigned long long u64;

__device__ __forceinline__ u64 fma2(u64 a, u64 b, u64 c) {
    u64 d;
    asm("fma.rn.f32x2 %0, %1, %2, %3;" : "=l"(d) : "l"(a), "l"(b), "l"(c));
    return d;
}
__device__ __forceinline__ u64 pack2(float v) {
    u64 r;
    asm("mov.b64 %0, {%1, %1};" : "=l"(r) : "f"(v));
    return r;
}
__device__ __forceinline__ u64 pack2f(float a, float b) {
    u64 r;
    asm("mov.b64 %0, {%1, %2};" : "=l"(r) : "f"(a), "f"(b));
    return r;
}
__device__ __forceinline__ float2 unpack2(u64 v) {
    float2 r;
    asm("mov.b64 {%0, %1}, %2;" : "=f"(r.x), "=f"(r.y) : "l"(v));
    return r;
}

__device__ __forceinline__ float fast_sigmoid(float x) {
    return __fdividef(1.0f, 1.0f + __expf(-x));
}
__device__ __forceinline__ float fast_tanh(float x) {
    float a = fabsf(x);
    float e = __expf(-2.0f * a);
    float r = __fdividef(1.0f - e, 1.0f + e);
    return copysignf(r, x);
}

// Two cell updates (one seq-pair) from packed gate pre-activations.
__device__ __forceinline__ u64 lstm_cell2(u64 ai, u64 af, u64 ag, u64 ao,
                                          float& cx, float& cy) {
    float2 vi = unpack2(ai), vf = unpack2(af), vg = unpack2(ag), vo = unpack2(ao);
    float igx = fast_sigmoid(vi.x), igy = fast_sigmoid(vi.y);
    float fgx = fast_sigmoid(vf.x), fgy = fast_sigmoid(vf.y);
    float ggx = fast_tanh(vg.x),    ggy = fast_tanh(vg.y);
    float ogx = fast_sigmoid(vo.x), ogy = fast_sigmoid(vo.y);
    cx = fmaf(fgx, cx, igx * ggx);
    cy = fmaf(fgy, cy, igy * ggy);
    return pack2f(ogx * fast_tanh(cx), ogy * fast_tanh(cy));
}

__global__ void __launch_bounds__(THREADS, 1)
lstm_fused_kernel(const float* __restrict__ x,
                  const float* __restrict__ Wih0, const float* __restrict__ Whh0,
                  const float* __restrict__ bih0, const float* __restrict__ bhh0,
                  const float* __restrict__ Wih1, const float* __restrict__ Whh1,
                  const float* __restrict__ bih1, const float* __restrict__ bhh1,
                  const float* __restrict__ W1, const float* __restrict__ b1,
                  const float* __restrict__ W2, const float* __restrict__ b2,
                  float* __restrict__ out, int batch) {
    extern __shared__ char smem_raw[];
    SmemW* s = reinterpret_cast<SmemW*>(smem_raw);

    const int tid = threadIdx.x;

    // ---- Stage weights: [dim][unit] float4 gate-quads ----
    for (int i = tid; i < IN_DIM * H_DIM; i += THREADS) {
        int k = i / H_DIM, u = i % H_DIM;
        s->wih0[k][u] = make_float4(Wih0[(0 * H_DIM + u) * IN_DIM + k],
                                    Wih0[(1 * H_DIM + u) * IN_DIM + k],
                                    Wih0[(2 * H_DIM + u) * IN_DIM + k],
                                    Wih0[(3 * H_DIM + u) * IN_DIM + k]);
    }
    for (int i = tid; i < H_DIM * H_DIM; i += THREADS) {
        int j = i / H_DIM, u = i % H_DIM;
        s->whh0[j][u] = make_float4(Whh0[(0 * H_DIM + u) * H_DIM + j],
                                    Whh0[(1 * H_DIM + u) * H_DIM + j],
                                    Whh0[(2 * H_DIM + u) * H_DIM + j],
                                    Whh0[(3 * H_DIM + u) * H_DIM + j]);
        s->wih1[j][u] = make_float4(Wih1[(0 * H_DIM + u) * H_DIM + j],
                                    Wih1[(1 * H_DIM + u) * H_DIM + j],
                                    Wih1[(2 * H_DIM + u) * H_DIM + j],
                                    Wih1[(3 * H_DIM + u) * H_DIM + j]);
        s->whh1[j][u] = make_float4(Whh1[(0 * H_DIM + u) * H_DIM + j],
                                    Whh1[(1 * H_DIM + u) * H_DIM + j],
                                    Whh1[(2 * H_DIM + u) * H_DIM + j],
                                    Whh1[(3 * H_DIM + u) * H_DIM + j]);
    }
    for (int u = tid; u < H_DIM; u += THREADS) {
        s->bg0[u] = make_float4(bih0[0 * H_DIM + u] + bhh0[0 * H_DIM + u],
                                bih0[1 * H_DIM + u] + bhh0[1 * H_DIM + u],
                                bih0[2 * H_DIM + u] + bhh0[2 * H_DIM + u],
                                bih0[3 * H_DIM + u] + bhh0[3 * H_DIM + u]);
        s->bg1[u] = make_float4(bih1[0 * H_DIM + u] + bhh1[0 * H_DIM + u],
                                bih1[1 * H_DIM + u] + bhh1[1 * H_DIM + u],
                                bih1[2 * H_DIM + u] + bhh1[2 * H_DIM + u],
                                bih1[3 * H_DIM + u] + bhh1[3 * H_DIM + u]);
    }
    __syncthreads();

    const int warp = tid >> 5;
    const int lane = tid & 31;           // lane = hidden unit index
    const int wglobal = blockIdx.x * WARPS_PER_BLOCK + warp;
    const int seq_base = wglobal * SEQ_PER_WARP;
    if (seq_base >= batch) return;       // batch % 8 == 0

    const float* xb = x + (size_t)seq_base * T_LEN * IN_DIM;
    const size_t seq_stride = (size_t)T_LEN * IN_DIM;

    // Pre-packed biases (duplicated per f32x2 half).
    float4 b0v = s->bg0[lane];
    float4 b1v = s->bg1[lane];
    const u64 bi0 = pack2(b0v.x), bf0 = pack2(b0v.y), bg0_ = pack2(b0v.z), bo0 = pack2(b0v.w);
    const u64 bi1 = pack2(b1v.x), bf1 = pack2(b1v.y), bg1_ = pack2(b1v.z), bo1 = pack2(b1v.w);

    // State: seq-pair packed h, scalar c.
    u64 h0p[4] = {0, 0, 0, 0};
    u64 h1p[4] = {0, 0, 0, 0};
    float c0f[8] = {0, 0, 0, 0, 0, 0, 0, 0};
    float c1f[8] = {0, 0, 0, 0, 0, 0, 0, 0};

    // x for t=0: lanes 0..15 hold x[s][0][lane] packed by seq-pair.
    u64 xp[4];
    {
        float xs[8];
#pragma unroll
        for (int ss = 0; ss < 8; ss++)
            xs[ss] = (lane < IN_DIM) ? __ldg(xb + ss * seq_stride + lane) : 0.f;
#pragma unroll
        for (int p = 0; p < 4; p++) xp[p] = pack2f(xs[2 * p], xs[2 * p + 1]);
    }

    for (int t = 0; t < T_LEN; t++) {
        // Prefetch next timestep x.
        u64 xpn[4] = {0, 0, 0, 0};
        if (t + 1 < T_LEN) {
            float xs[8];
#pragma unroll
            for (int ss = 0; ss < 8; ss++)
                xs[ss] = (lane < IN_DIM)
                             ? __ldg(xb + ss * seq_stride + (t + 1) * IN_DIM + lane)
                             : 0.f;
#pragma unroll
            for (int p = 0; p < 4; p++) xpn[p] = pack2f(xs[2 * p], xs[2 * p + 1]);
        }

        // ================= Layer 0 =================
        u64 ai[4], af[4], ag[4], ao[4];
#pragma unroll
        for (int p = 0; p < 4; p++) { ai[p] = bi0; af[p] = bf0; ag[p] = bg0_; ao[p] = bo0; }

#pragma unroll
        for (int k = 0; k < IN_DIM; k++) {
            u64 a2[4];
#pragma unroll
            for (int p = 0; p < 4; p++) a2[p] = __shfl_sync(FULLMASK, xp[p], k);
            float4 w = s->wih0[k][lane];
            u64 wi = pack2(w.x), wf = pack2(w.y), wg = pack2(w.z), wo = pack2(w.w);
#pragma unroll
            for (int p = 0; p < 4; p++) {
                ai[p] = fma2(wi, a2[p], ai[p]);
                af[p] = fma2(wf, a2[p], af[p]);
                ag[p] = fma2(wg, a2[p], ag[p]);
                ao[p] = fma2(wo, a2[p], ao[p]);
            }
        }
#pragma unroll
        for (int j = 0; j < H_DIM; j++) {
            u64 a2[4];
#pragma unroll
            for (int p = 0; p < 4; p++) a2[p] = __shfl_sync(FULLMASK, h0p[p], j);
            float4 w = s->whh0[j][lane];
            u64 wi = pack2(w.x), wf = pack2(w.y), wg = pack2(w.z), wo = pack2(w.w);
#pragma unroll
            for (int p = 0; p < 4; p++) {
                ai[p] = fma2(wi, a2[p], ai[p]);
                af[p] = fma2(wf, a2[p], af[p]);
                ag[p] = fma2(wg, a2[p], ag[p]);
                ao[p] = fma2(wo, a2[p], ao[p]);
            }
        }
        u64 h0n[4];
#pragma unroll
        for (int p = 0; p < 4; p++)
            h0n[p] = lstm_cell2(ai[p], af[p], ag[p], ao[p], c0f[2 * p], c0f[2 * p + 1]);

        // ================= Layer 1 =================
#pragma unroll
        for (int p = 0; p < 4; p++) { ai[p] = bi1; af[p] = bf1; ag[p] = bg1_; ao[p] = bo1; }

#pragma unroll
        for (int j = 0; j < H_DIM; j++) {
            u64 a2[4];
#pragma unroll
            for (int p = 0; p < 4; p++) a2[p] = __shfl_sync(FULLMASK, h0n[p], j);
            float4 w = s->wih1[j][lane];
            u64 wi = pack2(w.x), wf = pack2(w.y), wg = pack2(w.z), wo = pack2(w.w);
#pragma unroll
            for (int p = 0; p < 4; p++) {
                ai[p] = fma2(wi, a2[p], ai[p]);
                af[p] = fma2(wf, a2[p], af[p]);
                ag[p] = fma2(wg, a2[p], ag[p]);
                ao[p] = fma2(wo, a2[p], ao[p]);
            }
        }
#pragma unroll
        for (int j = 0; j < H_DIM; j++) {
            u64 a2[4];
#pragma unroll
            for (int p = 0; p < 4; p++) a2[p] = __shfl_sync(FULLMASK, h1p[p], j);
            float4 w = s->whh1[j][lane];
            u64 wi = pack2(w.x), wf = pack2(w.y), wg = pack2(w.z), wo = pack2(w.w);
#pragma unroll
            for (int p = 0; p < 4; p++) {
                ai[p] = fma2(wi, a2[p], ai[p]);
                af[p] = fma2(wf, a2[p], af[p]);
                ag[p] = fma2(wg, a2[p], ag[p]);
                ao[p] = fma2(wo, a2[p], ao[p]);
            }
        }
#pragma unroll
        for (int p = 0; p < 4; p++) {
            h1p[p] = lstm_cell2(ai[p], af[p], ag[p], ao[p], c1f[2 * p], c1f[2 * p + 1]);
            h0p[p] = h0n[p];
            xp[p] = xpn[p];
        }
    }

    // ---- Head: z = relu(h1 @ W1.T + b1); y = z @ W2.T + b2 ----
    // Lane m (<16) computes z[m] for all 4 seq-pairs.
    u64 z2[4];
    {
        float bm = (lane < 16) ? __ldg(b1 + lane) : 0.f;
#pragma unroll
        for (int p = 0; p < 4; p++) z2[p] = pack2(bm);
#pragma unroll
        for (int j = 0; j < H_DIM; j++) {
            u64 hj0 = __shfl_sync(FULLMASK, h1p[0], j);
            u64 hj1 = __shfl_sync(FULLMASK, h1p[1], j);
            u64 hj2 = __shfl_sync(FULLMASK, h1p[2], j);
            u64 hj3 = __shfl_sync(FULLMASK, h1p[3], j);
            float wm = (lane < 16) ? __ldg(W1 + lane * H_DIM + j) : 0.f;
            u64 wm2 = pack2(wm);
            z2[0] = fma2(wm2, hj0, z2[0]);
            z2[1] = fma2(wm2, hj1, z2[1]);
            z2[2] = fma2(wm2, hj2, z2[2]);
            z2[3] = fma2(wm2, hj3, z2[3]);
        }
    }
    float w2m = (lane < 16) ? __ldg(W2 + lane) : 0.f;
    float yv[8];
#pragma unroll
    for (int p = 0; p < 4; p++) {
        float2 z = unpack2(z2[p]);
        yv[2 * p]     = fmaxf(z.x, 0.f) * w2m;
        yv[2 * p + 1] = fmaxf(z.y, 0.f) * w2m;
    }
#pragma unroll
    for (int ss = 0; ss < 8; ss++) {
        float v = yv[ss];
#pragma unroll
        for (int off = 8; off >= 1; off >>= 1)
            v += __shfl_xor_sync(FULLMASK, v, off, 16);
        yv[ss] = v;
    }
    if (lane == 0) {
        float bias2 = __ldg(b2);
#pragma unroll
        for (int ss = 0; ss < 8; ss++) out[seq_base + ss] = yv[ss] + bias2;
    }
}

extern "C" void kernel_launch(void* const* d_in, const int* in_sizes, int n_in,
                              void* d_out, int out_size) {
    const float* x    = (const float*)d_in[0];
    const float* Wih0 = (const float*)d_in[1];
    const float* Whh0 = (const float*)d_in[2];
    const float* bih0 = (const float*)d_in[3];
    const float* bhh0 = (const float*)d_in[4];
    const float* Wih1 = (const float*)d_in[5];
    const float* Whh1 = (const float*)d_in[6];
    const float* bih1 = (const float*)d_in[7];
    const float* bhh1 = (const float*)d_in[8];
    const float* W1   = (const float*)d_in[9];
    const float* b1   = (const float*)d_in[10];
    const float* W2   = (const float*)d_in[11];
    const float* b2   = (const float*)d_in[12];
    float* out = (float*)d_out;

    int batch = in_sizes[0] / (T_LEN * IN_DIM);  // 4096

    cudaFuncSetAttribute(lstm_fused_kernel,
                         cudaFuncAttributeMaxDynamicSharedMemorySize,
                         (int)sizeof(SmemW));

    int warps_needed = (batch + SEQ_PER_WARP - 1) / SEQ_PER_WARP;        // 512
    int blocks = (warps_needed + WARPS_PER_BLOCK - 1) / WARPS_PER_BLOCK; // 128
    lstm_fused_kernel<<<blocks, THREADS, sizeof(SmemW)>>>(
        x, Wih0, Whh0, bih0, bhh0, Wih1, Whh1, bih1, bhh1,
        W1, b1, W2, b2, out, batch);
}

// round 5
// speedup vs baseline: 1.9256x; 1.5456x over previous
#include <cuda_runtime.h>

// 2-layer LSTM (IN=16, H=32, T=512, B=4096) + MLP head, fully fused.
// R5: lane = hidden unit; warp = 4 sequences. f32x2 packing over INPUT-DIM
// PAIRS (j-pairs): smem weights hold (w[2jp], w[2jp+1]) per gate, LDS.128
// lands them in aligned register pairs -> FFMA2 with NO duplication MOVs.
// Accumulators are u64 per (gate, seq); lo half sums even j, hi half odd j;
// one FADD merges at the end. Activation pairs broadcast via 64-bit shfl.
// 1024 warps (147 blocks x 7 warps, ~7/SM) for latency hiding.

#define FULLMASK 0xffffffffu

constexpr int T_LEN = 512;
constexpr int IN_DIM = 16;
constexpr int H_DIM = 32;
constexpr int SEQ_PER_WARP = 4;
constexpr int WARPS_PER_BLOCK = 7;
constexpr int THREADS = WARPS_PER_BLOCK * 32;

// Weight arrays: [jp][unit] float4.
//  A-array = (wi[2jp], wi[2jp+1], wf[2jp], wf[2jp+1])
//  B-array = (wg[2jp], wg[2jp+1], wo[2jp], wo[2jp+1])
struct SmemW {
    float4 ihA0[IN_DIM / 2][H_DIM];
    float4 ihB0[IN_DIM / 2][H_DIM];
    float4 hhA0[H_DIM / 2][H_DIM];
    float4 hhB0[H_DIM / 2][H_DIM];
    float4 ihA1[H_DIM / 2][H_DIM];
    float4 ihB1[H_DIM / 2][H_DIM];
    float4 hhA1[H_DIM / 2][H_DIM];
    float4 hhB1[H_DIM / 2][H_DIM];
    float4 bg0[H_DIM];   // (bi, bf, bg, bo) per unit (bih+bhh)
    float4 bg1[H_DIM];
};

typedef unsigned long long u64;

__device__ __forceinline__ u64 fma2(u64 a, u64 b, u64 c) {
    u64 d;
    asm("fma.rn.f32x2 %0, %1, %2, %3;" : "=l"(d) : "l"(a), "l"(b), "l"(c));
    return d;
}
__device__ __forceinline__ u64 pack2f(float a, float b) {
    u64 r;
    asm("mov.b64 %0, {%1, %2};" : "=l"(r) : "f"(a), "f"(b));
    return r;
}
__device__ __forceinline__ float2 unpack2(u64 v) {
    float2 r;
    asm("mov.b64 {%0, %1}, %2;" : "=f"(r.x), "=f"(r.y) : "l"(v));
    return r;
}
__device__ __forceinline__ float hsum2(u64 v) {
    float2 r = unpack2(v);
    return r.x + r.y;
}

__device__ __forceinline__ float fast_sigmoid(float x) {
    return __fdividef(1.0f, 1.0f + __expf(-x));
}
__device__ __forceinline__ float fast_tanh(float x) {
    float a = fabsf(x);
    float e = __expf(-2.0f * a);
    float r = __fdividef(1.0f - e, 1.0f + e);
    return copysignf(r, x);
}

__global__ void __launch_bounds__(THREADS, 1)
lstm_fused_kernel(const float* __restrict__ x,
                  const float* __restrict__ Wih0, const float* __restrict__ Whh0,
                  const float* __restrict__ bih0, const float* __restrict__ bhh0,
                  const float* __restrict__ Wih1, const float* __restrict__ Whh1,
                  const float* __restrict__ bih1, const float* __restrict__ bhh1,
                  const float* __restrict__ W1, const float* __restrict__ b1,
                  const float* __restrict__ W2, const float* __restrict__ b2,
                  float* __restrict__ out, int batch) {
    extern __shared__ char smem_raw[];
    SmemW* s = reinterpret_cast<SmemW*>(smem_raw);

    const int tid = threadIdx.x;

    // ---- Stage weights as gate j-pairs ----
    // Wih0: [4H][IN]
    for (int i = tid; i < (IN_DIM / 2) * H_DIM; i += THREADS) {
        int jp = i / H_DIM, u = i % H_DIM;
        int j0 = 2 * jp, j1 = 2 * jp + 1;
        s->ihA0[jp][u] = make_float4(Wih0[(0 * H_DIM + u) * IN_DIM + j0],
                                     Wih0[(0 * H_DIM + u) * IN_DIM + j1],
                                     Wih0[(1 * H_DIM + u) * IN_DIM + j0],
                                     Wih0[(1 * H_DIM + u) * IN_DIM + j1]);
        s->ihB0[jp][u] = make_float4(Wih0[(2 * H_DIM + u) * IN_DIM + j0],
                                     Wih0[(2 * H_DIM + u) * IN_DIM + j1],
                                     Wih0[(3 * H_DIM + u) * IN_DIM + j0],
                                     Wih0[(3 * H_DIM + u) * IN_DIM + j1]);
    }
    // H x H matrices: [4H][H]
    for (int i = tid; i < (H_DIM / 2) * H_DIM; i += THREADS) {
        int jp = i / H_DIM, u = i % H_DIM;
        int j0 = 2 * jp, j1 = 2 * jp + 1;
        s->hhA0[jp][u] = make_float4(Whh0[(0 * H_DIM + u) * H_DIM + j0],
                                     Whh0[(0 * H_DIM + u) * H_DIM + j1],
                                     Whh0[(1 * H_DIM + u) * H_DIM + j0],
                                     Whh0[(1 * H_DIM + u) * H_DIM + j1]);
        s->hhB0[jp][u] = make_float4(Whh0[(2 * H_DIM + u) * H_DIM + j0],
                                     Whh0[(2 * H_DIM + u) * H_DIM + j1],
                                     Whh0[(3 * H_DIM + u) * H_DIM + j0],
                                     Whh0[(3 * H_DIM + u) * H_DIM + j1]);
        s->ihA1[jp][u] = make_float4(Wih1[(0 * H_DIM + u) * H_DIM + j0],
                                     Wih1[(0 * H_DIM + u) * H_DIM + j1],
                                     Wih1[(1 * H_DIM + u) * H_DIM + j0],
                                     Wih1[(1 * H_DIM + u) * H_DIM + j1]);
        s->ihB1[jp][u] = make_float4(Wih1[(2 * H_DIM + u) * H_DIM + j0],
                                     Wih1[(2 * H_DIM + u) * H_DIM + j1],
                                     Wih1[(3 * H_DIM + u) * H_DIM + j0],
                                     Wih1[(3 * H_DIM + u) * H_DIM + j1]);
        s->hhA1[jp][u] = make_float4(Whh1[(0 * H_DIM + u) * H_DIM + j0],
                                     Whh1[(0 * H_DIM + u) * H_DIM + j1],
                                     Whh1[(1 * H_DIM + u) * H_DIM + j0],
                                     Whh1[(1 * H_DIM + u) * H_DIM + j1]);
        s->hhB1[jp][u] = make_float4(Whh1[(2 * H_DIM + u) * H_DIM + j0],
                                     Whh1[(2 * H_DIM + u) * H_DIM + j1],
                                     Whh1[(3 * H_DIM + u) * H_DIM + j0],
                                     Whh1[(3 * H_DIM + u) * H_DIM + j1]);
    }
    for (int u = tid; u < H_DIM; u += THREADS) {
        s->bg0[u] = make_float4(bih0[0 * H_DIM + u] + bhh0[0 * H_DIM + u],
                                bih0[1 * H_DIM + u] + bhh0[1 * H_DIM + u],
                                bih0[2 * H_DIM + u] + bhh0[2 * H_DIM + u],
                                bih0[3 * H_DIM + u] + bhh0[3 * H_DIM + u]);
        s->bg1[u] = make_float4(bih1[0 * H_DIM + u] + bhh1[0 * H_DIM + u],
                                bih1[1 * H_DIM + u] + bhh1[1 * H_DIM + u],
                                bih1[2 * H_DIM + u] + bhh1[2 * H_DIM + u],
                                bih1[3 * H_DIM + u] + bhh1[3 * H_DIM + u]);
    }
    __syncthreads();

    const int warp = tid >> 5;
    const int lane = tid & 31;    // lane = hidden unit
    const int wglobal = blockIdx.x * WARPS_PER_BLOCK + warp;
    const int seq_base = wglobal * SEQ_PER_WARP;
    if (seq_base >= batch) return;  // batch % 4 == 0

    const float* xb = x + (size_t)seq_base * T_LEN * IN_DIM;
    const size_t seq_stride = (size_t)T_LEN * IN_DIM;

    const float4 b0v = s->bg0[lane];
    const float4 b1v = s->bg1[lane];

    // State: scalar per (unit=lane, seq) h & c, plus j-pair-packed h for bcast.
    float h1f[SEQ_PER_WARP] = {0, 0, 0, 0};
    float c0f[SEQ_PER_WARP] = {0, 0, 0, 0};
    float c1f[SEQ_PER_WARP] = {0, 0, 0, 0};
    u64 h0p[SEQ_PER_WARP] = {0, 0, 0, 0};  // lane L<16: (h0[2L], h0[2L+1])
    u64 h1p[SEQ_PER_WARP] = {0, 0, 0, 0};

    // x pairs: lane L<8 holds (x[2L], x[2L+1]) per seq.
    u64 xp[SEQ_PER_WARP];
#pragma unroll
    for (int ss = 0; ss < SEQ_PER_WARP; ss++) {
        float2 v = make_float2(0.f, 0.f);
        if (lane < IN_DIM / 2)
            v = *reinterpret_cast<const float2*>(xb + ss * seq_stride + 2 * lane);
        xp[ss] = pack2f(v.x, v.y);
    }

    for (int t = 0; t < T_LEN; t++) {
        // Prefetch next x.
        u64 xpn[SEQ_PER_WARP] = {0, 0, 0, 0};
        if (t + 1 < T_LEN) {
#pragma unroll
            for (int ss = 0; ss < SEQ_PER_WARP; ss++) {
                float2 v = make_float2(0.f, 0.f);
                if (lane < IN_DIM / 2)
                    v = *reinterpret_cast<const float2*>(
                        xb + ss * seq_stride + (t + 1) * IN_DIM + 2 * lane);
                xpn[ss] = pack2f(v.x, v.y);
            }
        }

        // ================= Layer 0 =================
        u64 ai[4], af[4], ag[4], ao[4];  // [seq], lo=even j, hi=odd j
#pragma unroll
        for (int ss = 0; ss < 4; ss++) {
            ai[ss] = pack2f(b0v.x, 0.f);
            af[ss] = pack2f(b0v.y, 0.f);
            ag[ss] = pack2f(b0v.z, 0.f);
            ao[ss] = pack2f(b0v.w, 0.f);
        }
#pragma unroll
        for (int jp = 0; jp < IN_DIM / 2; jp++) {
            u64 a2[4];
#pragma unroll
            for (int ss = 0; ss < 4; ss++) a2[ss] = __shfl_sync(FULLMASK, xp[ss], jp);
            ulonglong2 wA = *reinterpret_cast<const ulonglong2*>(&s->ihA0[jp][lane]);
            ulonglong2 wB = *reinterpret_cast<const ulonglong2*>(&s->ihB0[jp][lane]);
#pragma unroll
            for (int ss = 0; ss < 4; ss++) {
                ai[ss] = fma2(wA.x, a2[ss], ai[ss]);
                af[ss] = fma2(wA.y, a2[ss], af[ss]);
                ag[ss] = fma2(wB.x, a2[ss], ag[ss]);
                ao[ss] = fma2(wB.y, a2[ss], ao[ss]);
            }
        }
#pragma unroll
        for (int jp = 0; jp < H_DIM / 2; jp++) {
            u64 a2[4];
#pragma unroll
            for (int ss = 0; ss < 4; ss++) a2[ss] = __shfl_sync(FULLMASK, h0p[ss], jp);
            ulonglong2 wA = *reinterpret_cast<const ulonglong2*>(&s->hhA0[jp][lane]);
            ulonglong2 wB = *reinterpret_cast<const ulonglong2*>(&s->hhB0[jp][lane]);
#pragma unroll
            for (int ss = 0; ss < 4; ss++) {
                ai[ss] = fma2(wA.x, a2[ss], ai[ss]);
                af[ss] = fma2(wA.y, a2[ss], af[ss]);
                ag[ss] = fma2(wB.x, a2[ss], ag[ss]);
                ao[ss] = fma2(wB.y, a2[ss], ao[ss]);
            }
        }
        float h0n[4];
#pragma unroll
        for (int ss = 0; ss < 4; ss++) {
            float ig = fast_sigmoid(hsum2(ai[ss]));
            float fg = fast_sigmoid(hsum2(af[ss]));
            float gg = fast_tanh(hsum2(ag[ss]));
            float og = fast_sigmoid(hsum2(ao[ss]));
            c0f[ss] = fmaf(fg, c0f[ss], ig * gg);
            h0n[ss] = og * fast_tanh(c0f[ss]);
        }
        // Pair-pack h0n for broadcasts (valid on lanes 0..15).
        u64 h0np[4];
#pragma unroll
        for (int ss = 0; ss < 4; ss++) {
            float lo = __shfl_sync(FULLMASK, h0n[ss], 2 * lane);
            float hi = __shfl_sync(FULLMASK, h0n[ss], 2 * lane + 1);
            h0np[ss] = pack2f(lo, hi);
        }

        // ================= Layer 1 =================
#pragma unroll
        for (int ss = 0; ss < 4; ss++) {
            ai[ss] = pack2f(b1v.x, 0.f);
            af[ss] = pack2f(b1v.y, 0.f);
            ag[ss] = pack2f(b1v.z, 0.f);
            ao[ss] = pack2f(b1v.w, 0.f);
        }
#pragma unroll
        for (int jp = 0; jp < H_DIM / 2; jp++) {
            u64 a2[4];
#pragma unroll
            for (int ss = 0; ss < 4; ss++) a2[ss] = __shfl_sync(FULLMASK, h0np[ss], jp);
            ulonglong2 wA = *reinterpret_cast<const ulonglong2*>(&s->ihA1[jp][lane]);
            ulonglong2 wB = *reinterpret_cast<const ulonglong2*>(&s->ihB1[jp][lane]);
#pragma unroll
            for (int ss = 0; ss < 4; ss++) {
                ai[ss] = fma2(wA.x, a2[ss], ai[ss]);
                af[ss] = fma2(wA.y, a2[ss], af[ss]);
                ag[ss] = fma2(wB.x, a2[ss], ag[ss]);
                ao[ss] = fma2(wB.y, a2[ss], ao[ss]);
            }
        }
#pragma unroll
        for (int jp = 0; jp < H_DIM / 2; jp++) {
            u64 a2[4];
#pragma unroll
            for (int ss = 0; ss < 4; ss++) a2[ss] = __shfl_sync(FULLMASK, h1p[ss], jp);
            ulonglong2 wA = *reinterpret_cast<const ulonglong2*>(&s->hhA1[jp][lane]);
            ulonglong2 wB = *reinterpret_cast<const ulonglong2*>(&s->hhB1[jp][lane]);
#pragma unroll
            for (int ss = 0; ss < 4; ss++) {
                ai[ss] = fma2(wA.x, a2[ss], ai[ss]);
                af[ss] = fma2(wA.y, a2[ss], af[ss]);
                ag[ss] = fma2(wB.x, a2[ss], ag[ss]);
                ao[ss] = fma2(wB.y, a2[ss], ao[ss]);
            }
        }
#pragma unroll
        for (int ss = 0; ss < 4; ss++) {
            float ig = fast_sigmoid(hsum2(ai[ss]));
            float fg = fast_sigmoid(hsum2(af[ss]));
            float gg = fast_tanh(hsum2(ag[ss]));
            float og = fast_sigmoid(hsum2(ao[ss]));
            c1f[ss] = fmaf(fg, c1f[ss], ig * gg);
            h1f[ss] = og * fast_tanh(c1f[ss]);
        }
        // Pair-pack h1 for next step's Whh1 broadcasts.
#pragma unroll
        for (int ss = 0; ss < 4; ss++) {
            float lo = __shfl_sync(FULLMASK, h1f[ss], 2 * lane);
            float hi = __shfl_sync(FULLMASK, h1f[ss], 2 * lane + 1);
            h1p[ss] = pack2f(lo, hi);
            h0p[ss] = h0np[ss];
            xp[ss] = xpn[ss];
        }
    }

    // ---- Head: z = relu(h1 @ W1.T + b1); y = z @ W2.T + b2 ----
    float z[4];
    {
        float bm = (lane < 16) ? __ldg(b1 + lane) : 0.f;
#pragma unroll
        for (int ss = 0; ss < 4; ss++) z[ss] = bm;
#pragma unroll
        for (int j = 0; j < H_DIM; j++) {
            float wm = (lane < 16) ? __ldg(W1 + lane * H_DIM + j) : 0.f;
#pragma unroll
            for (int ss = 0; ss < 4; ss++) {
                float hj = __shfl_sync(FULLMASK, h1f[ss], j);
                z[ss] = fmaf(wm, hj, z[ss]);
            }
        }
    }
    float w2m = (lane < 16) ? __ldg(W2 + lane) : 0.f;
    float bias2 = __ldg(b2);
#pragma unroll
    for (int ss = 0; ss < 4; ss++) {
        float v = fmaxf(z[ss], 0.f) * w2m;
#pragma unroll
        for (int off = 8; off >= 1; off >>= 1)
            v += __shfl_xor_sync(FULLMASK, v, off, 16);
        if (lane == 0) out[seq_base + ss] = v + bias2;
    }
}

extern "C" void kernel_launch(void* const* d_in, const int* in_sizes, int n_in,
                              void* d_out, int out_size) {
    const float* x    = (const float*)d_in[0];
    const float* Wih0 = (const float*)d_in[1];
    const float* Whh0 = (const float*)d_in[2];
    const float* bih0 = (const float*)d_in[3];
    const float* bhh0 = (const float*)d_in[4];
    const float* Wih1 = (const float*)d_in[5];
    const float* Whh1 = (const float*)d_in[6];
    const float* bih1 = (const float*)d_in[7];
    const float* bhh1 = (const float*)d_in[8];
    const float* W1   = (const float*)d_in[9];
    const float* b1   = (const float*)d_in[10];
    const float* W2   = (const float*)d_in[11];
    const float* b2   = (const float*)d_in[12];
    float* out = (float*)d_out;

    int batch = in_sizes[0] / (T_LEN * IN_DIM);  // 4096

    cudaFuncSetAttribute(lstm_fused_kernel,
                         cudaFuncAttributeMaxDynamicSharedMemorySize,
                         (int)sizeof(SmemW));

    int warps_needed = (batch + SEQ_PER_WARP - 1) / SEQ_PER_WARP;        // 1024
    int blocks = (warps_needed + WARPS_PER_BLOCK - 1) / WARPS_PER_BLOCK; // 147
    lstm_fused_kernel<<<blocks, THREADS, sizeof(SmemW)>>>(
        x, Wih0, Whh0, bih0, bhh0, Wih1, Whh1, bih1, bhh1,
        W1, b1, W2, b2, out, batch);
}